// round 13
// baseline (speedup 1.0000x reference)
#include <cuda_runtime.h>
#include <cstdint>

#define THREADS 256
#define TILE_R  128

// ---- SMEM byte offsets ----
#define OFF_V    0        // fp32 V/T: 128 x 132 x 4 = 67584
#define OFF_VB   67584    // bf16 V:   128 x 68 u32  = 34816
#define OFF_W1   102400   // 3 x 16384 (W1 ring)
#define OFF_W2   151552   // 3 x 16384 (W2 ring)
#define OFF_PAR  200704   // 2560 floats
#define SMEM_BYTES 210944

#define VSTR  132
#define VBSTR 68

// pre-packed bf16 uint4 B-fragment weight images (two adjacent n8-tiles per uint4)
__device__ uint4 g_w1img[2][8][1024];   // GEMM1 B: K=128, N=64/chunk
__device__ uint4 g_w2img[2][8][1024];   // GEMM2 B: K=64/chunk, N=128

__device__ __forceinline__ uint32_t smem_u32(const void* p){
    uint32_t a;
    asm("{ .reg .u64 t; cvta.to.shared.u64 t, %1; cvt.u32.u64 %0, t; }"
        : "=r"(a) : "l"(p));
    return a;
}
__device__ __forceinline__ uint32_t bf2(float lo, float hi){
    uint32_t r;
    asm("cvt.rn.bf16x2.f32 %0, %1, %2;" : "=r"(r) : "f"(hi), "f"(lo));
    return r;
}
// fast GELU (tanh form)
__device__ __forceinline__ float gelu_fast(float x){
    float t = x * x;
    float s = fmaf(t, 0.10293971f, 2.3021293f);
    float z = x * s;
    float e;
    asm("ex2.approx.f32 %0, %1;" : "=f"(e) : "f"(z));
    float rc;
    asm("rcp.approx.f32 %0, %1;" : "=f"(rc) : "f"(1.0f + e));
    return x - x * rc;
}

#define MMA_BF16(d, a, b0, b1) asm volatile( \
    "mma.sync.aligned.m16n8k16.row.col.f32.bf16.bf16.f32 " \
    "{%0,%1,%2,%3},{%4,%5,%6,%7},{%8,%9},{%0,%1,%2,%3};" \
    : "+f"((d)[0]), "+f"((d)[1]), "+f"((d)[2]), "+f"((d)[3]) \
    : "r"((a)[0]), "r"((a)[1]), "r"((a)[2]), "r"((a)[3]), \
      "r"(b0), "r"(b1))

#define LDSM4(r, addr) asm volatile( \
    "ldmatrix.sync.aligned.m8n8.x4.shared.b16 {%0,%1,%2,%3}, [%4];" \
    : "=r"((r)[0]), "=r"((r)[1]), "=r"((r)[2]), "=r"((r)[3]) : "r"(addr))

#define CP_ASYNC16(dst, src) asm volatile( \
    "cp.async.cg.shared.global [%0], [%1], 16;" :: "r"(dst), "l"(src))
#define CP_COMMIT() asm volatile("cp.async.commit_group;" ::: "memory")
#define CP_WAIT(n)  asm volatile("cp.async.wait_group %0;" :: "n"(n) : "memory")

// stage W1[k] + W2[k] (2 x 16KB) in ONE commit group: 256 thr x 8 x 16B
__device__ __forceinline__ void stage_pair(uint32_t d1, const void* s1,
                                           uint32_t d2, const void* s2, int tid){
    const float4* a = (const float4*)s1;
    const float4* b = (const float4*)s2;
#pragma unroll
    for (int i = 0; i < 4; ++i){
        CP_ASYNC16(d1 + (uint32_t)(tid + i*256) * 16u, a + tid + i*256);
        CP_ASYNC16(d2 + (uint32_t)(tid + i*256) * 16u, b + tid + i*256);
    }
    CP_COMMIT();
}

// load GEMM1 A operand (16 rows x K=128) into registers: 8 LDSM4
__device__ __forceinline__ void load_afr(uint32_t Afr[8][4], uint32_t a1ad){
#pragma unroll
    for (int ks = 0; ks < 8; ++ks)
        LDSM4(Afr[ks], a1ad + ks * 32u);
}

// convert acc1 (+bias, GELU) into GEMM2 A-fragments, all in registers.
// acc1 tile: 16 rows x 64 cols; A2[kt] = m16k16 fragment for k-tile kt.
__device__ __forceinline__ void convert_h(const float acc1[8][4], uint32_t A2[4][4],
                                          const float* __restrict__ pB1, int qcol){
#pragma unroll
    for (int kt = 0; kt < 4; ++kt){
        const float b0 = pB1[16*kt + 2*qcol],     b1 = pB1[16*kt + 2*qcol + 1];
        const float b2 = pB1[16*kt + 8 + 2*qcol], b3 = pB1[16*kt + 9 + 2*qcol];
        A2[kt][0] = bf2(gelu_fast(acc1[2*kt][0] + b0),   gelu_fast(acc1[2*kt][1] + b1));
        A2[kt][1] = bf2(gelu_fast(acc1[2*kt][2] + b0),   gelu_fast(acc1[2*kt][3] + b1));
        A2[kt][2] = bf2(gelu_fast(acc1[2*kt+1][0] + b2), gelu_fast(acc1[2*kt+1][1] + b3));
        A2[kt][3] = bf2(gelu_fast(acc1[2*kt+1][2] + b2), gelu_fast(acc1[2*kt+1][3] + b3));
    }
}

// interleaved MMA phase: GEMM2[p] (A2 regs x w2) and GEMM1[p+1] (Afr x w1n)
__device__ __forceinline__ void phase_mma(float acc1[8][4], float acc2[16][4],
                                          const uint32_t Afr[8][4],
                                          const uint32_t A2[4][4],
                                          const uint4* __restrict__ w1n,
                                          const uint4* __restrict__ w2,
                                          int lane, bool doG1, bool doG2){
    if (doG1){
#pragma unroll
        for (int b = 0; b < 8; ++b)
#pragma unroll
            for (int d = 0; d < 4; ++d) acc1[b][d] = 0.f;
    }
#pragma unroll
    for (int s = 0; s < 4; ++s){
        if (doG2){
#pragma unroll
            for (int pp = 0; pp < 8; ++pp){
                uint4 B = w2[(s * 8 + pp) * 32 + lane];
                MMA_BF16(acc2[2*pp],   A2[s], B.x, B.y);
                MMA_BF16(acc2[2*pp+1], A2[s], B.z, B.w);
            }
        }
        if (doG1){
#pragma unroll
            for (int kk = 0; kk < 2; ++kk){
                const int ks = 2*s + kk;
#pragma unroll
                for (int pp = 0; pp < 4; ++pp){
                    uint4 B = w1n[(ks * 4 + pp) * 32 + lane];
                    MMA_BF16(acc1[2*pp],   Afr[ks], B.x, B.y);
                    MMA_BF16(acc1[2*pp+1], Afr[ks], B.z, B.w);
                }
            }
        }
    }
}

// ---------------- prep: pack bf16 uint4 B-fragment weight images ----------------
__global__ void prep_kernel(const float* __restrict__ W1a, const float* __restrict__ W2a,
                            const float* __restrict__ W1b, const float* __restrict__ W2b)
{
    int idx  = blockIdx.x * 256 + threadIdx.x;   // 0..32767
    int isW2 = idx >> 14;
    int r    = idx & 16383;
    int m    = r >> 13;
    int c    = (r >> 10) & 7;
    int s    = r & 1023;
    int lane = s & 31;
    int t    = s >> 5;                            // 0..31
    if (!isW2){
        int ks = t >> 2, p = t & 3;
        const float* W1 = m ? W1b : W1a;
        int k  = ks * 16 + (lane & 3) * 2;
        int n0 = c * 64 + (2 * p) * 8 + (lane >> 2);
        int n1 = n0 + 8;
        uint4 v;
        v.x = bf2(W1[(size_t)k * 512 + n0],       W1[(size_t)(k + 1) * 512 + n0]);
        v.y = bf2(W1[(size_t)(k + 8) * 512 + n0], W1[(size_t)(k + 9) * 512 + n0]);
        v.z = bf2(W1[(size_t)k * 512 + n1],       W1[(size_t)(k + 1) * 512 + n1]);
        v.w = bf2(W1[(size_t)(k + 8) * 512 + n1], W1[(size_t)(k + 9) * 512 + n1]);
        g_w1img[m][c][s] = v;
    } else {
        int ks = t >> 3, p = t & 7;
        const float* W2 = m ? W2b : W2a;
        int k  = c * 64 + ks * 16 + (lane & 3) * 2;
        int n0 = (2 * p) * 8 + (lane >> 2);
        int n1 = n0 + 8;
        uint4 v;
        v.x = bf2(W2[(size_t)k * 128 + n0],       W2[(size_t)(k + 1) * 128 + n0]);
        v.y = bf2(W2[(size_t)(k + 8) * 128 + n0], W2[(size_t)(k + 9) * 128 + n0]);
        v.z = bf2(W2[(size_t)k * 128 + n1],       W2[(size_t)(k + 1) * 128 + n1]);
        v.w = bf2(W2[(size_t)(k + 8) * 128 + n1], W2[(size_t)(k + 9) * 128 + n1]);
        g_w2img[m][c][s] = v;
    }
}

// ---------------- main kernel (warp-local dataflow) ----------------
extern "C" __global__ void __launch_bounds__(THREADS, 1)
tsal_wl_kernel(const float* __restrict__ x,
               const float* __restrict__ bo_time, const float* __restrict__ bo_recv,
               const float* __restrict__ g1, const float* __restrict__ be1,
               const float* __restrict__ g2, const float* __restrict__ be2,
               const float* __restrict__ g3, const float* __restrict__ be3,
               const float* __restrict__ g4, const float* __restrict__ be4,
               const float* __restrict__ b1a, const float* __restrict__ b2a,
               const float* __restrict__ b1b, const float* __restrict__ b2b,
               float* __restrict__ out)
{
    extern __shared__ __align__(16) char smb[];
    float*    sV  = (float*)(smb + OFF_V);
    uint32_t* sVb = (uint32_t*)(smb + OFF_VB);
    float*    par = (float*)(smb + OFF_PAR);
    const uint4* w1buf[3] = { (const uint4*)(smb + OFF_W1),
                              (const uint4*)(smb + OFF_W1 + 16384),
                              (const uint4*)(smb + OFF_W1 + 32768) };
    const uint4* w2buf[3] = { (const uint4*)(smb + OFF_W2),
                              (const uint4*)(smb + OFF_W2 + 16384),
                              (const uint4*)(smb + OFF_W2 + 32768) };
    uint32_t w1addr[3], w2addr[3];
#pragma unroll
    for (int i = 0; i < 3; ++i){
        w1addr[i] = smem_u32(smb + OFF_W1 + i * 16384);
        w2addr[i] = smem_u32(smb + OFF_W2 + i * 16384);
    }

    const int tid  = threadIdx.x;
    const int lane = tid & 31, wid = tid >> 5;   // 8 warps, warp w owns rows 16w..16w+15
    const int qrow = lane >> 2, qcol = lane & 3;
    const int lrow = tid >> 1, lhalf = tid & 1;  // LN: 2 threads/row (warp-local rows)

    // ldmatrix per-lane source coordinates (m16k16 .x4)
    const int lmRow = ((lane >> 3) & 1) * 8 + (lane & 7);
    const int lmCol = (lane >> 4) * 4;           // u32 offset
    const uint32_t a1ad = smem_u32(sVb)
                        + (uint32_t)((wid * 16 + lmRow) * VBSTR + lmCol) * 4u;

    // prefetch W[0], W[1] (two commit groups)
    stage_pair(w1addr[0], &g_w1img[0][0][0], w2addr[0], &g_w2img[0][0][0], tid);
    stage_pair(w1addr[1], &g_w1img[0][1][0], w2addr[1], &g_w2img[0][1][0], tid);

    // stage params
    for (int i = tid; i < 128; i += THREADS){
        par[i]        = bo_time[i]; par[128 + i]  = bo_recv[i];
        par[256 + i]  = g1[i];      par[384 + i]  = be1[i];
        par[512 + i]  = g2[i];      par[640 + i]  = be2[i];
        par[768 + i]  = g3[i];      par[896 + i]  = be3[i];
        par[1024 + i] = g4[i];      par[1152 + i] = be4[i];
        par[1280 + i] = b2a[i];     par[1408 + i] = b2b[i];
    }
    for (int i = tid; i < 512; i += THREADS){
        par[1536 + i] = b1a[i];     par[2048 + i] = b1b[i];
    }
    __syncthreads();   // params visible

    // ---- LN1: v1 = LN(x + bo_time) -> sV (fp32) + sVb (bf16), warp-local rows ----
    const size_t grow = (size_t)blockIdx.x * TILE_R + lrow;
    {
        float4 v[16];
        float s = 0.f, q = 0.f;
#pragma unroll
        for (int i = 0; i < 16; ++i){
            int c = lhalf * 64 + 4 * i;
            float4 a = *(const float4*)(x + grow * 128 + c);
            a.x += par[c + 0]; a.y += par[c + 1]; a.z += par[c + 2]; a.w += par[c + 3];
            v[i] = a;
            s += a.x + a.y + a.z + a.w;
            q = fmaf(a.x, a.x, q); q = fmaf(a.y, a.y, q);
            q = fmaf(a.z, a.z, q); q = fmaf(a.w, a.w, q);
        }
        s += __shfl_xor_sync(0xffffffffu, s, 1, 2);
        q += __shfl_xor_sync(0xffffffffu, q, 1, 2);
        float mu = s * 0.0078125f;
        float rs = rsqrtf(q * 0.0078125f - mu * mu + 1e-5f);
#pragma unroll
        for (int i = 0; i < 16; ++i){
            int c = lhalf * 64 + 4 * i;
            float4 a = v[i], o;
            o.x = (a.x - mu) * rs * par[256 + c + 0] + par[384 + c + 0];
            o.y = (a.y - mu) * rs * par[256 + c + 1] + par[384 + c + 1];
            o.z = (a.z - mu) * rs * par[256 + c + 2] + par[384 + c + 2];
            o.w = (a.w - mu) * rs * par[256 + c + 3] + par[384 + c + 3];
            *(float4*)(sV + lrow * VSTR + c) = o;
            sVb[lrow * VBSTR + (c >> 1)]     = bf2(o.x, o.y);
            sVb[lrow * VBSTR + (c >> 1) + 1] = bf2(o.z, o.w);
        }
    }
    __syncwarp();     // sVb rows (warp-local) visible to warp's LDSM

    uint32_t Afr[8][4];
    load_afr(Afr, a1ad);

    float acc1[8][4], acc2[16][4];
#pragma unroll
    for (int b = 0; b < 16; ++b)
#pragma unroll
        for (int d = 0; d < 4; ++d) acc2[b][d] = 0.f;

    // ---- preamble: GEMM1[0] ----
    CP_WAIT(1);        // W[0] resident (W[1] may be pending)
    {
        uint32_t A2d[4][4];
        phase_mma(acc1, acc2, Afr, A2d, w1buf[0], w2buf[0], lane, true, false);
    }

    // ---- 16 phases: convert H[p] (regs), run GEMM2[p] + GEMM1[p+1] ----
    for (int p = 0; p < 16; ++p){
        __syncthreads();   // all warps done with phase p-1 -> buf[(p+2)%3] free
        if (p <= 13)
            stage_pair(w1addr[(p + 2) % 3], &g_w1img[(p + 2) >> 3][(p + 2) & 7][0],
                       w2addr[(p + 2) % 3], &g_w2img[(p + 2) >> 3][(p + 2) & 7][0], tid);
        if (p <= 13) CP_WAIT(1);   // W[p+1] arrived (only W[p+2] pending)
        else         CP_WAIT(0);

        const int ch = p & 7;
        const float* pB1 = par + ((p >= 8) ? 2048 : 1536) + ch * 64;

        uint32_t A2[4][4];
        convert_h(acc1, A2, pB1, qcol);

        if (ch != 7){
            phase_mma(acc1, acc2, Afr, A2,
                      w1buf[(p + 1) % 3], w2buf[p % 3], lane, true, true);
        } else {
            // GEMM2 only, then warp-local boundary processing
            phase_mma(acc1, acc2, Afr, A2,
                      w1buf[0], w2buf[p % 3], lane, false, true);
            const float* pB2 = par + ((p >= 8) ? 1408 : 1280);

            // T = V + D2 + b2, in place in sV (warp tile 16x128)
            const int r0 = wid * 16 + qrow;
#pragma unroll
            for (int nt = 0; nt < 16; ++nt){
                const int cb = nt * 8 + 2 * qcol;
                const float b20 = pB2[cb], b21 = pB2[cb + 1];
                float2* v0p = (float2*)(sV + r0 * VSTR + cb);
                float2* v1p = (float2*)(sV + (r0 + 8) * VSTR + cb);
                float2 v0 = *v0p, v1 = *v1p;
                v0.x += acc2[nt][0] + b20; v0.y += acc2[nt][1] + b21;
                v1.x += acc2[nt][2] + b20; v1.y += acc2[nt][3] + b21;
                *v0p = v0; *v1p = v1;
            }
            __syncwarp();

            // LN on T rows (2 threads/row, warp-local)
            float4 v[16];
            float s = 0.f, q = 0.f;
#pragma unroll
            for (int i = 0; i < 16; ++i){
                int c = lhalf * 64 + 4 * i;
                float4 a = *(const float4*)(sV + lrow * VSTR + c);
                v[i] = a;
                s += a.x + a.y + a.z + a.w;
                q = fmaf(a.x, a.x, q); q = fmaf(a.y, a.y, q);
                q = fmaf(a.z, a.z, q); q = fmaf(a.w, a.w, q);
            }
            s += __shfl_xor_sync(0xffffffffu, s, 1, 2);
            q += __shfl_xor_sync(0xffffffffu, q, 1, 2);
            float mu = s * 0.0078125f;
            float rs = rsqrtf(q * 0.0078125f - mu * mu + 1e-5f);

            if (p == 7){
                // v2 = LN2(T); v3 = LN3(v2 + bo_recv) -> sV + sVb
                float s2 = 0.f, q2 = 0.f;
#pragma unroll
                for (int i = 0; i < 16; ++i){
                    int c = lhalf * 64 + 4 * i;
                    float4 a = v[i], o;
                    o.x = (a.x - mu) * rs * par[512 + c + 0] + par[640 + c + 0] + par[128 + c + 0];
                    o.y = (a.y - mu) * rs * par[512 + c + 1] + par[640 + c + 1] + par[128 + c + 1];
                    o.z = (a.z - mu) * rs * par[512 + c + 2] + par[640 + c + 2] + par[128 + c + 2];
                    o.w = (a.w - mu) * rs * par[512 + c + 3] + par[640 + c + 3] + par[128 + c + 3];
                    v[i] = o;
                    s2 += o.x + o.y + o.z + o.w;
                    q2 = fmaf(o.x, o.x, q2); q2 = fmaf(o.y, o.y, q2);
                    q2 = fmaf(o.z, o.z, q2); q2 = fmaf(o.w, o.w, q2);
                }
                s2 += __shfl_xor_sync(0xffffffffu, s2, 1, 2);
                q2 += __shfl_xor_sync(0xffffffffu, q2, 1, 2);
                float mu2 = s2 * 0.0078125f;
                float rs2 = rsqrtf(q2 * 0.0078125f - mu2 * mu2 + 1e-5f);
#pragma unroll
                for (int i = 0; i < 16; ++i){
                    int c = lhalf * 64 + 4 * i;
                    float4 a = v[i], o;
                    o.x = (a.x - mu2) * rs2 * par[768 + c + 0] + par[896 + c + 0];
                    o.y = (a.y - mu2) * rs2 * par[768 + c + 1] + par[896 + c + 1];
                    o.z = (a.z - mu2) * rs2 * par[768 + c + 2] + par[896 + c + 2];
                    o.w = (a.w - mu2) * rs2 * par[768 + c + 3] + par[896 + c + 3];
                    *(float4*)(sV + lrow * VSTR + c) = o;
                    sVb[lrow * VBSTR + (c >> 1)]     = bf2(o.x, o.y);
                    sVb[lrow * VBSTR + (c >> 1) + 1] = bf2(o.z, o.w);
                }
                __syncwarp();           // sVb warp-local rows visible

                load_afr(Afr, a1ad);    // new V -> reload resident A
#pragma unroll
                for (int b = 0; b < 16; ++b)
#pragma unroll
                    for (int d = 0; d < 4; ++d) acc2[b][d] = 0.f;
                // GEMM1[8] (w1buf[8%3=2]; W[8] arrived at this phase's CP_WAIT)
                uint32_t A2d[4][4];
                phase_mma(acc1, acc2, Afr, A2d, w1buf[2], w2buf[0], lane, true, false);
            } else {
                // p == 15: out = LN4(T) -> GMEM
#pragma unroll
                for (int i = 0; i < 16; ++i){
                    int c = lhalf * 64 + 4 * i;
                    float4 a = v[i], o;
                    o.x = (a.x - mu) * rs * par[1024 + c + 0] + par[1152 + c + 0];
                    o.y = (a.y - mu) * rs * par[1024 + c + 1] + par[1152 + c + 1];
                    o.z = (a.z - mu) * rs * par[1024 + c + 2] + par[1152 + c + 2];
                    o.w = (a.w - mu) * rs * par[1024 + c + 3] + par[1152 + c + 3];
                    *(float4*)(out + grow * 128 + c) = o;
                }
            }
        }
    }
}

extern "C" void kernel_launch(void* const* d_in, const int* in_sizes, int n_in,
                              void* d_out, int out_size)
{
    const float* x       = (const float*)d_in[0];
    // d_in[1]=router (dead), d_in[3]=bo_send (dead)
    const float* bo_time = (const float*)d_in[2];
    const float* bo_recv = (const float*)d_in[4];
    const float* g1 = (const float*)d_in[5],  *be1 = (const float*)d_in[6];
    const float* g2 = (const float*)d_in[7],  *be2 = (const float*)d_in[8];
    const float* g3 = (const float*)d_in[9],  *be3 = (const float*)d_in[10];
    const float* g4 = (const float*)d_in[11], *be4 = (const float*)d_in[12];
    const float* W1a = (const float*)d_in[13], *b1a = (const float*)d_in[14];
    const float* W2a = (const float*)d_in[15], *b2a = (const float*)d_in[16];
    const float* W1b = (const float*)d_in[17], *b1b = (const float*)d_in[18];
    const float* W2b = (const float*)d_in[19], *b2b = (const float*)d_in[20];
    float* out = (float*)d_out;

    int rows   = in_sizes[0] / 128;   // 131072
    int blocks = rows / TILE_R;       // 1024

    prep_kernel<<<128, 256>>>(W1a, W2a, W1b, W2b);

    cudaFuncSetAttribute(tsal_wl_kernel,
                         cudaFuncAttributeMaxDynamicSharedMemorySize, SMEM_BYTES);
    tsal_wl_kernel<<<blocks, THREADS, SMEM_BYTES>>>(
        x, bo_time, bo_recv,
        g1, be1, g2, be2, g3, be3, g4, be4,
        b1a, b2a, b1b, b2b, out);
}

// round 14
// speedup vs baseline: 1.3403x; 1.3403x over previous
#include <cuda_runtime.h>
#include <cuda_fp16.h>
#include <cstdint>

#define THREADS 256
#define TILE_R  128

// ---- SMEM byte offsets (per CTA, 110592 B total -> 2 CTAs/SM) ----
#define OFF_VH   0        // fp16 V: 128 x 68 u32 = 34816
#define OFF_W1   34816    // 2 x 16384 (W1 ring)
#define OFF_W2   67584    // 2 x 16384 (W2 ring)
#define OFF_PAR  100352   // 2560 floats
#define SMEM_BYTES 110592

#define VBSTR 68

// pre-packed fp16 uint4 B-fragment weight images (two adjacent n8-tiles per uint4)
__device__ uint4 g_w1img[2][8][1024];   // GEMM1 B: K=128, N=64/chunk
__device__ uint4 g_w2img[2][8][1024];   // GEMM2 B: K=64/chunk, N=128

__device__ __forceinline__ uint32_t smem_u32(const void* p){
    uint32_t a;
    asm("{ .reg .u64 t; cvta.to.shared.u64 t, %1; cvt.u32.u64 %0, t; }"
        : "=r"(a) : "l"(p));
    return a;
}
__device__ __forceinline__ uint32_t h2u(float lo, float hi){
    __half2 h = __floats2half2_rn(lo, hi);
    return *(uint32_t*)&h;
}
__device__ __forceinline__ float2 u2f2(uint32_t u){
    __half2 h = *(__half2*)&u;
    return __half22float2(h);
}
// fast GELU (tanh form)
__device__ __forceinline__ float gelu_fast(float x){
    float t = x * x;
    float s = fmaf(t, 0.10293971f, 2.3021293f);
    float z = x * s;
    float e;
    asm("ex2.approx.f32 %0, %1;" : "=f"(e) : "f"(z));
    float rc;
    asm("rcp.approx.f32 %0, %1;" : "=f"(rc) : "f"(1.0f + e));
    return x - x * rc;
}

// f16-accumulator MMA: D,C are 2 regs (half2 x2)
#define MMA_F16(d, a, b0, b1) asm volatile( \
    "mma.sync.aligned.m16n8k16.row.col.f16.f16.f16.f16 " \
    "{%0,%1},{%2,%3,%4,%5},{%6,%7},{%0,%1};" \
    : "+r"((d)[0]), "+r"((d)[1]) \
    : "r"((a)[0]), "r"((a)[1]), "r"((a)[2]), "r"((a)[3]), \
      "r"(b0), "r"(b1))

#define LDSM4(r, addr) asm volatile( \
    "ldmatrix.sync.aligned.m8n8.x4.shared.b16 {%0,%1,%2,%3}, [%4];" \
    : "=r"((r)[0]), "=r"((r)[1]), "=r"((r)[2]), "=r"((r)[3]) : "r"(addr))

#define CP_ASYNC16(dst, src) asm volatile( \
    "cp.async.cg.shared.global [%0], [%1], 16;" :: "r"(dst), "l"(src))
#define CP_COMMIT() asm volatile("cp.async.commit_group;" ::: "memory")
#define CP_WAIT(n)  asm volatile("cp.async.wait_group %0;" :: "n"(n) : "memory")

// stage one 16KB image: 256 thr x 4 x 16B (no commit)
__device__ __forceinline__ void stage_one(uint32_t dst, const void* src, int tid){
    const float4* s4 = (const float4*)src;
#pragma unroll
    for (int i = 0; i < 4; ++i)
        CP_ASYNC16(dst + (uint32_t)(tid + i*256) * 16u, s4 + tid + i*256);
}

// ---------------- prep: pack fp16 uint4 B-fragment weight images ----------------
__global__ void prep_kernel(const float* __restrict__ W1a, const float* __restrict__ W2a,
                            const float* __restrict__ W1b, const float* __restrict__ W2b)
{
    int idx  = blockIdx.x * 256 + threadIdx.x;   // 0..32767
    int isW2 = idx >> 14;
    int r    = idx & 16383;
    int m    = r >> 13;
    int c    = (r >> 10) & 7;
    int s    = r & 1023;
    int lane = s & 31;
    int t    = s >> 5;                            // 0..31
    if (!isW2){
        int ks = t >> 2, p = t & 3;
        const float* W1 = m ? W1b : W1a;
        int k  = ks * 16 + (lane & 3) * 2;
        int n0 = c * 64 + (2 * p) * 8 + (lane >> 2);
        int n1 = n0 + 8;
        uint4 v;
        v.x = h2u(W1[(size_t)k * 512 + n0],       W1[(size_t)(k + 1) * 512 + n0]);
        v.y = h2u(W1[(size_t)(k + 8) * 512 + n0], W1[(size_t)(k + 9) * 512 + n0]);
        v.z = h2u(W1[(size_t)k * 512 + n1],       W1[(size_t)(k + 1) * 512 + n1]);
        v.w = h2u(W1[(size_t)(k + 8) * 512 + n1], W1[(size_t)(k + 9) * 512 + n1]);
        g_w1img[m][c][s] = v;
    } else {
        int ks = t >> 3, p = t & 7;
        const float* W2 = m ? W2b : W2a;
        int k  = c * 64 + ks * 16 + (lane & 3) * 2;
        int n0 = (2 * p) * 8 + (lane >> 2);
        int n1 = n0 + 8;
        uint4 v;
        v.x = h2u(W2[(size_t)k * 128 + n0],       W2[(size_t)(k + 1) * 128 + n0]);
        v.y = h2u(W2[(size_t)(k + 8) * 128 + n0], W2[(size_t)(k + 9) * 128 + n0]);
        v.z = h2u(W2[(size_t)k * 128 + n1],       W2[(size_t)(k + 1) * 128 + n1]);
        v.w = h2u(W2[(size_t)(k + 8) * 128 + n1], W2[(size_t)(k + 9) * 128 + n1]);
        g_w2img[m][c][s] = v;
    }
}

// interleaved MMA phase: GEMM2[p] (A2 regs x w2) and GEMM1[p+1] (A1 LDSM x w1n)
__device__ __forceinline__ void phase_mma(uint32_t acc1[8][2], uint32_t acc2[16][2],
                                          uint32_t a1ad,
                                          const uint32_t A2[4][4],
                                          const uint4* __restrict__ w1n,
                                          const uint4* __restrict__ w2,
                                          int lane, bool doG1, bool doG2){
    if (doG1){
#pragma unroll
        for (int b = 0; b < 8; ++b){ acc1[b][0] = 0u; acc1[b][1] = 0u; }
    }
#pragma unroll
    for (int s = 0; s < 4; ++s){
        if (doG2){
#pragma unroll
            for (int pp = 0; pp < 8; ++pp){
                uint4 B = w2[(s * 8 + pp) * 32 + lane];
                MMA_F16(acc2[2*pp],   A2[s], B.x, B.y);
                MMA_F16(acc2[2*pp+1], A2[s], B.z, B.w);
            }
        }
        if (doG1){
#pragma unroll
            for (int kk = 0; kk < 2; ++kk){
                const int ks = 2*s + kk;
                uint32_t A1[4];
                LDSM4(A1, a1ad + ks * 32u);
#pragma unroll
                for (int pp = 0; pp < 4; ++pp){
                    uint4 B = w1n[(ks * 4 + pp) * 32 + lane];
                    MMA_F16(acc1[2*pp],   A1, B.x, B.y);
                    MMA_F16(acc1[2*pp+1], A1, B.z, B.w);
                }
            }
        }
    }
}

// convert acc1 (+bias, GELU) into GEMM2 A-fragments, all in registers
__device__ __forceinline__ void convert_h(const uint32_t acc1[8][2], uint32_t A2[4][4],
                                          const float* __restrict__ pB1, int qcol){
#pragma unroll
    for (int kt = 0; kt < 4; ++kt){
        const float b0 = pB1[16*kt + 2*qcol],     b1 = pB1[16*kt + 2*qcol + 1];
        const float b2 = pB1[16*kt + 8 + 2*qcol], b3 = pB1[16*kt + 9 + 2*qcol];
#pragma unroll
        for (int rr = 0; rr < 2; ++rr){
            float2 f0 = u2f2(acc1[2*kt][rr]);
            float2 f1 = u2f2(acc1[2*kt+1][rr]);
            A2[kt][rr]     = h2u(gelu_fast(f0.x + b0), gelu_fast(f0.y + b1));
            A2[kt][rr + 2] = h2u(gelu_fast(f1.x + b2), gelu_fast(f1.y + b3));
        }
    }
}

// ---------------- main kernel (warp-local, fp16, 2 CTAs/SM) ----------------
extern "C" __global__ void __launch_bounds__(THREADS, 2)
tsal_f16_kernel(const float* __restrict__ x,
                const float* __restrict__ bo_time, const float* __restrict__ bo_recv,
                const float* __restrict__ g1, const float* __restrict__ be1,
                const float* __restrict__ g2, const float* __restrict__ be2,
                const float* __restrict__ g3, const float* __restrict__ be3,
                const float* __restrict__ g4, const float* __restrict__ be4,
                const float* __restrict__ b1a, const float* __restrict__ b2a,
                const float* __restrict__ b1b, const float* __restrict__ b2b,
                float* __restrict__ out)
{
    extern __shared__ __align__(16) char smb[];
    uint32_t* sVh = (uint32_t*)(smb + OFF_VH);
    float*    par = (float*)(smb + OFF_PAR);
    const uint4* w1buf[2] = { (const uint4*)(smb + OFF_W1), (const uint4*)(smb + OFF_W1 + 16384) };
    const uint4* w2buf[2] = { (const uint4*)(smb + OFF_W2), (const uint4*)(smb + OFF_W2 + 16384) };
    const uint32_t w1addr[2] = { smem_u32(smb + OFF_W1), smem_u32(smb + OFF_W1 + 16384) };
    const uint32_t w2addr[2] = { smem_u32(smb + OFF_W2), smem_u32(smb + OFF_W2 + 16384) };

    const int tid  = threadIdx.x;
    const int lane = tid & 31, wid = tid >> 5;   // 8 warps, warp w owns rows 16w..16w+15
    const int qrow = lane >> 2, qcol = lane & 3;
    const int lrow = tid >> 1, lhalf = tid & 1;  // LN1: 2 threads/row (warp-local rows)

    const int lmRow = ((lane >> 3) & 1) * 8 + (lane & 7);
    const int lmCol = (lane >> 4) * 4;           // u32 offset
    const uint32_t a1ad = smem_u32(sVh)
                        + (uint32_t)((wid * 16 + lmRow) * VBSTR + lmCol) * 4u;

    // preamble prefetch: group0 = {W1[0], W2[0]}, group1 = {W1[1]}
    stage_one(w1addr[0], &g_w1img[0][0][0], tid);
    stage_one(w2addr[0], &g_w2img[0][0][0], tid);
    CP_COMMIT();
    stage_one(w1addr[1], &g_w1img[0][1][0], tid);
    CP_COMMIT();

    // stage params
    for (int i = tid; i < 128; i += THREADS){
        par[i]        = bo_time[i]; par[128 + i]  = bo_recv[i];
        par[256 + i]  = g1[i];      par[384 + i]  = be1[i];
        par[512 + i]  = g2[i];      par[640 + i]  = be2[i];
        par[768 + i]  = g3[i];      par[896 + i]  = be3[i];
        par[1024 + i] = g4[i];      par[1152 + i] = be4[i];
        par[1280 + i] = b2a[i];     par[1408 + i] = b2b[i];
    }
    for (int i = tid; i < 512; i += THREADS){
        par[1536 + i] = b1a[i];     par[2048 + i] = b1b[i];
    }
    __syncthreads();   // params visible

    // ---- LN1: v1 = LN(x + bo_time) -> sVh (fp16), warp-local rows ----
    const size_t grow = (size_t)blockIdx.x * TILE_R + lrow;
    {
        float4 v[16];
        float s = 0.f, q = 0.f;
#pragma unroll
        for (int i = 0; i < 16; ++i){
            int c = lhalf * 64 + 4 * i;
            float4 a = *(const float4*)(x + grow * 128 + c);
            a.x += par[c + 0]; a.y += par[c + 1]; a.z += par[c + 2]; a.w += par[c + 3];
            v[i] = a;
            s += a.x + a.y + a.z + a.w;
            q = fmaf(a.x, a.x, q); q = fmaf(a.y, a.y, q);
            q = fmaf(a.z, a.z, q); q = fmaf(a.w, a.w, q);
        }
        s += __shfl_xor_sync(0xffffffffu, s, 1, 2);
        q += __shfl_xor_sync(0xffffffffu, q, 1, 2);
        float mu = s * 0.0078125f;
        float rs = rsqrtf(q * 0.0078125f - mu * mu + 1e-5f);
#pragma unroll
        for (int i = 0; i < 16; ++i){
            int c = lhalf * 64 + 4 * i;
            float4 a = v[i];
            float o0 = (a.x - mu) * rs * par[256 + c + 0] + par[384 + c + 0];
            float o1 = (a.y - mu) * rs * par[256 + c + 1] + par[384 + c + 1];
            float o2 = (a.z - mu) * rs * par[256 + c + 2] + par[384 + c + 2];
            float o3 = (a.w - mu) * rs * par[256 + c + 3] + par[384 + c + 3];
            sVh[lrow * VBSTR + (c >> 1)]     = h2u(o0, o1);
            sVh[lrow * VBSTR + (c >> 1) + 1] = h2u(o2, o3);
        }
    }
    __syncwarp();     // warp-local sVh rows visible to this warp's LDSM

    uint32_t acc1[8][2], acc2[16][2];
#pragma unroll
    for (int b = 0; b < 16; ++b){ acc2[b][0] = 0u; acc2[b][1] = 0u; }

    // ---- preamble: GEMM1[0] (needs group0 done; group1 may pend) ----
    CP_WAIT(1);
    {
        uint32_t A2d[4][4];
        phase_mma(acc1, acc2, a1ad, A2d, w1buf[0], w2buf[0], lane, true, false);
    }

    // ---- 16 phases ----
    for (int p = 0; p < 16; ++p){
        __syncthreads();   // frees W1 buf[p&1] (held W1[p]) and W2 buf[(p+1)&1] (held W2[p-1])
        bool st = false;
        if (p + 2 <= 15){ stage_one(w1addr[p & 1], &g_w1img[(p + 2) >> 3][(p + 2) & 7][0], tid); st = true; }
        if (p + 1 <= 15){ stage_one(w2addr[(p + 1) & 1], &g_w2img[(p + 1) >> 3][(p + 1) & 7][0], tid); st = true; }
        if (st) CP_COMMIT();
        if (st) CP_WAIT(1);   // all groups except newest done -> W1[p+1], W2[p] resident
        else    CP_WAIT(0);

        const int ch = p & 7;
        const float* pB1 = par + ((p >= 8) ? 2048 : 1536) + ch * 64;

        uint32_t A2[4][4];
        convert_h(acc1, A2, pB1, qcol);

        if (ch != 7){
            phase_mma(acc1, acc2, a1ad, A2,
                      w1buf[(p + 1) & 1], w2buf[p & 1], lane, true, true);
        } else {
            phase_mma(acc1, acc2, a1ad, A2, w1buf[0], w2buf[p & 1], lane, false, true);
            const float* pB2 = par + ((p >= 8) ? 1408 : 1280);
            const int r0 = wid * 16 + qrow, r1 = r0 + 8;

            // pass 1: T stats per row (T = V + D2 + b2), T stays virtual
            float s0 = 0.f, q0 = 0.f, s1 = 0.f, q1 = 0.f;
#pragma unroll
            for (int pp = 0; pp < 16; ++pp){
                const int cb = pp * 8 + 2 * qcol;
                const float b20 = pB2[cb], b21 = pB2[cb + 1];
                float2 v0 = u2f2(sVh[r0 * VBSTR + 4*pp + qcol]);
                float2 v1 = u2f2(sVh[r1 * VBSTR + 4*pp + qcol]);
                float2 d0 = u2f2(acc2[pp][0]);
                float2 d1 = u2f2(acc2[pp][1]);
                float t00 = v0.x + d0.x + b20, t01 = v0.y + d0.y + b21;
                float t10 = v1.x + d1.x + b20, t11 = v1.y + d1.y + b21;
                s0 += t00 + t01; q0 = fmaf(t00, t00, q0); q0 = fmaf(t01, t01, q0);
                s1 += t10 + t11; q1 = fmaf(t10, t10, q1); q1 = fmaf(t11, t11, q1);
            }
            s0 += __shfl_xor_sync(0xffffffffu, s0, 1, 4); s0 += __shfl_xor_sync(0xffffffffu, s0, 2, 4);
            q0 += __shfl_xor_sync(0xffffffffu, q0, 1, 4); q0 += __shfl_xor_sync(0xffffffffu, q0, 2, 4);
            s1 += __shfl_xor_sync(0xffffffffu, s1, 1, 4); s1 += __shfl_xor_sync(0xffffffffu, s1, 2, 4);
            q1 += __shfl_xor_sync(0xffffffffu, q1, 1, 4); q1 += __shfl_xor_sync(0xffffffffu, q1, 2, 4);
            float mu0 = s0 * 0.0078125f, rs0 = rsqrtf(q0 * 0.0078125f - mu0*mu0 + 1e-5f);
            float mu1 = s1 * 0.0078125f, rs1 = rsqrtf(q1 * 0.0078125f - mu1*mu1 + 1e-5f);

            if (p == 7){
                // pass 2: v2 = LN2(T)+bo_recv, stats of it
                float t0s = 0.f, t0q = 0.f, t1s = 0.f, t1q = 0.f;
#pragma unroll
                for (int pp = 0; pp < 16; ++pp){
                    const int cb = pp * 8 + 2 * qcol;
                    const float b20 = pB2[cb], b21 = pB2[cb + 1];
                    float2 v0 = u2f2(sVh[r0 * VBSTR + 4*pp + qcol]);
                    float2 v1 = u2f2(sVh[r1 * VBSTR + 4*pp + qcol]);
                    float2 d0 = u2f2(acc2[pp][0]);
                    float2 d1 = u2f2(acc2[pp][1]);
                    float u00 = ((v0.x + d0.x + b20) - mu0)*rs0*par[512+cb]   + par[640+cb]   + par[128+cb];
                    float u01 = ((v0.y + d0.y + b21) - mu0)*rs0*par[512+cb+1] + par[640+cb+1] + par[128+cb+1];
                    float u10 = ((v1.x + d1.x + b20) - mu1)*rs1*par[512+cb]   + par[640+cb]   + par[128+cb];
                    float u11 = ((v1.y + d1.y + b21) - mu1)*rs1*par[512+cb+1] + par[640+cb+1] + par[128+cb+1];
                    t0s += u00 + u01; t0q = fmaf(u00,u00,t0q); t0q = fmaf(u01,u01,t0q);
                    t1s += u10 + u11; t1q = fmaf(u10,u10,t1q); t1q = fmaf(u11,u11,t1q);
                }
                t0s += __shfl_xor_sync(0xffffffffu, t0s, 1, 4); t0s += __shfl_xor_sync(0xffffffffu, t0s, 2, 4);
                t0q += __shfl_xor_sync(0xffffffffu, t0q, 1, 4); t0q += __shfl_xor_sync(0xffffffffu, t0q, 2, 4);
                t1s += __shfl_xor_sync(0xffffffffu, t1s, 1, 4); t1s += __shfl_xor_sync(0xffffffffu, t1s, 2, 4);
                t1q += __shfl_xor_sync(0xffffffffu, t1q, 1, 4); t1q += __shfl_xor_sync(0xffffffffu, t1q, 2, 4);
                float m20 = t0s * 0.0078125f, r20 = rsqrtf(t0q * 0.0078125f - m20*m20 + 1e-5f);
                float m21 = t1s * 0.0078125f, r21 = rsqrtf(t1q * 0.0078125f - m21*m21 + 1e-5f);

                // pass 3: v3 = LN3(v2) -> sVh
#pragma unroll
                for (int pp = 0; pp < 16; ++pp){
                    const int cb = pp * 8 + 2 * qcol;
                    const float b20 = pB2[cb], b21 = pB2[cb + 1];
                    float2 v0 = u2f2(sVh[r0 * VBSTR + 4*pp + qcol]);
                    float2 v1 = u2f2(sVh[r1 * VBSTR + 4*pp + qcol]);
                    float2 d0 = u2f2(acc2[pp][0]);
                    float2 d1 = u2f2(acc2[pp][1]);
                    float u00 = ((v0.x + d0.x + b20) - mu0)*rs0*par[512+cb]   + par[640+cb]   + par[128+cb];
                    float u01 = ((v0.y + d0.y + b21) - mu0)*rs0*par[512+cb+1] + par[640+cb+1] + par[128+cb+1];
                    float u10 = ((v1.x + d1.x + b20) - mu1)*rs1*par[512+cb]   + par[640+cb]   + par[128+cb];
                    float u11 = ((v1.y + d1.y + b21) - mu1)*rs1*par[512+cb+1] + par[640+cb+1] + par[128+cb+1];
                    float w00 = (u00 - m20)*r20*par[768+cb]   + par[896+cb];
                    float w01 = (u01 - m20)*r20*par[768+cb+1] + par[896+cb+1];
                    float w10 = (u10 - m21)*r21*par[768+cb]   + par[896+cb];
                    float w11 = (u11 - m21)*r21*par[768+cb+1] + par[896+cb+1];
                    sVh[r0 * VBSTR + 4*pp + qcol] = h2u(w00, w01);
                    sVh[r1 * VBSTR + 4*pp + qcol] = h2u(w10, w11);
                }
                __syncwarp();

#pragma unroll
                for (int b = 0; b < 16; ++b){ acc2[b][0] = 0u; acc2[b][1] = 0u; }
                // GEMM1[8] (W1[8] in buf[(8)&1]=buf[0], resident via this phase's wait)
                uint32_t A2d[4][4];
                phase_mma(acc1, acc2, a1ad, A2d, w1buf[0], w2buf[0], lane, true, false);
            } else {
                // p == 15: out = LN4(T) -> GMEM (scattered float2 stores)
                const size_t gr0 = (size_t)blockIdx.x * TILE_R + r0;
                const size_t gr1 = gr0 + 8;
#pragma unroll
                for (int pp = 0; pp < 16; ++pp){
                    const int cb = pp * 8 + 2 * qcol;
                    const float b20 = pB2[cb], b21 = pB2[cb + 1];
                    float2 v0 = u2f2(sVh[r0 * VBSTR + 4*pp + qcol]);
                    float2 v1 = u2f2(sVh[r1 * VBSTR + 4*pp + qcol]);
                    float2 d0 = u2f2(acc2[pp][0]);
                    float2 d1 = u2f2(acc2[pp][1]);
                    float2 o0, o1;
                    o0.x = ((v0.x + d0.x + b20) - mu0)*rs0*par[1024+cb]   + par[1152+cb];
                    o0.y = ((v0.y + d0.y + b21) - mu0)*rs0*par[1024+cb+1] + par[1152+cb+1];
                    o1.x = ((v1.x + d1.x + b20) - mu1)*rs1*par[1024+cb]   + par[1152+cb];
                    o1.y = ((v1.y + d1.y + b21) - mu1)*rs1*par[1024+cb+1] + par[1152+cb+1];
                    *(float2*)(out + gr0 * 128 + cb) = o0;
                    *(float2*)(out + gr1 * 128 + cb) = o1;
                }
            }
        }
    }
}

extern "C" void kernel_launch(void* const* d_in, const int* in_sizes, int n_in,
                              void* d_out, int out_size)
{
    const float* x       = (const float*)d_in[0];
    // d_in[1]=router (dead), d_in[3]=bo_send (dead)
    const float* bo_time = (const float*)d_in[2];
    const float* bo_recv = (const float*)d_in[4];
    const float* g1 = (const float*)d_in[5],  *be1 = (const float*)d_in[6];
    const float* g2 = (const float*)d_in[7],  *be2 = (const float*)d_in[8];
    const float* g3 = (const float*)d_in[9],  *be3 = (const float*)d_in[10];
    const float* g4 = (const float*)d_in[11], *be4 = (const float*)d_in[12];
    const float* W1a = (const float*)d_in[13], *b1a = (const float*)d_in[14];
    const float* W2a = (const float*)d_in[15], *b2a = (const float*)d_in[16];
    const float* W1b = (const float*)d_in[17], *b1b = (const float*)d_in[18];
    const float* W2b = (const float*)d_in[19], *b2b = (const float*)d_in[20];
    float* out = (float*)d_out;

    int rows   = in_sizes[0] / 128;   // 131072
    int blocks = rows / TILE_R;       // 1024

    prep_kernel<<<128, 256>>>(W1a, W2a, W1b, W2b);

    cudaFuncSetAttribute(tsal_f16_kernel,
                         cudaFuncAttributeMaxDynamicSharedMemorySize, SMEM_BYTES);
    tsal_f16_kernel<<<blocks, THREADS, SMEM_BYTES>>>(
        x, bo_time, bo_recv,
        g1, be1, g2, be2, g3, be3, g4, be4,
        b1a, b2a, b1b, b2b, out);
}